// round 11
// baseline (speedup 1.0000x reference)
#include <cuda_runtime.h>

#define RED_NB 912    // 6 blocks/SM x 152 SMs — one exact wave for K1
#define TRF_NB 1216   // 8 blocks/SM x 152 SMs — one exact wave for K2

typedef unsigned long long u64;

// Device-global scratch (no allocations allowed).
static __device__ double g_part[RED_NB][9]; // per-block partials
static __device__ float  g_par[12];         // basis rows (right,up,fwd)[9], refPos[3]
static __device__ int    g_cnt;             // arrival counter (self-resetting)

// ---- packed f32x2 helpers (Blackwell; PTX-only, ptxas won't auto-fuse) ----
__device__ __forceinline__ u64 pk2(float lo, float hi) {
    u64 r;
    asm("mov.b64 %0, {%1, %2};" : "=l"(r) : "f"(lo), "f"(hi));
    return r;
}
__device__ __forceinline__ void fma2(u64& d, u64 a, u64 b) {   // d += a*b (2 lanes)
    asm("fma.rn.f32x2 %0, %1, %2, %3;" : "=l"(d) : "l"(a), "l"(b), "l"(d));
}
__device__ __forceinline__ void add2(u64& d, u64 a) {          // d += a (2 lanes)
    asm("add.rn.f32x2 %0, %1, %2;" : "=l"(d) : "l"(a), "l"(d));
}
__device__ __forceinline__ float unpk_sum(u64 v) {
    unsigned lo, hi;
    asm("mov.b64 {%0, %1}, %2;" : "=r"(lo), "=r"(hi) : "l"(v));
    return __uint_as_float(lo) + __uint_as_float(hi);
}

// K1: covariance reduce over rows 0..2 using packed f32x2 math (halves the
// fma-pipe instruction count — the prior kernel was issue-bound at 21 B/cyc/SM).
// Last-arriving block finishes the sum and runs the Newton eigensolve.
__global__ void __launch_bounds__(256, 6) k_reduce(const float* __restrict__ x,
                                                   const float* __restrict__ ra, int T) {
    const int nv = T >> 2;
    const size_t Ts = (size_t)T;
    const int tid = threadIdx.x;
    const int gid = blockIdx.x * 256 + tid;
    const int stride = gridDim.x * 256;
    const int NB = gridDim.x;

    {
        const float4* __restrict__ x0 = (const float4*)(x);
        const float4* __restrict__ x1 = (const float4*)(x + Ts);
        const float4* __restrict__ x2 = (const float4*)(x + 2 * Ts);

        u64 acc2[9];
#pragma unroll
        for (int k = 0; k < 9; ++k) acc2[k] = 0ull;   // (0.0f, 0.0f)

        for (int i = gid; i < nv; i += stride) {
            float4 v0 = x0[i], v1 = x1[i], v2 = x2[i];
#pragma unroll
            for (int h = 0; h < 2; ++h) {
                u64 a = (h == 0) ? pk2(v0.x, v0.y) : pk2(v0.z, v0.w);
                u64 b = (h == 0) ? pk2(v1.x, v1.y) : pk2(v1.z, v1.w);
                u64 c = (h == 0) ? pk2(v2.x, v2.y) : pk2(v2.z, v2.w);
                add2(acc2[0], a); add2(acc2[1], b); add2(acc2[2], c);
                fma2(acc2[3], a, a); fma2(acc2[4], b, b); fma2(acc2[5], c, c);
                fma2(acc2[6], a, b); fma2(acc2[7], a, c); fma2(acc2[8], b, c);
            }
        }

        float acc[9];
#pragma unroll
        for (int k = 0; k < 9; ++k) acc[k] = unpk_sum(acc2[k]);

        for (int t = (nv << 2) + gid; t < T; t += stride) {  // scalar tail
            float a = x[t], b = x[Ts + t], c = x[2 * Ts + t];
            acc[0] += a;     acc[1] += b;     acc[2] += c;
            acc[3] += a * a; acc[4] += b * b; acc[5] += c * c;
            acc[6] += a * b; acc[7] += a * c; acc[8] += b * c;
        }

#pragma unroll
        for (int k = 0; k < 9; ++k) {
            float v = acc[k];
#pragma unroll
            for (int off = 16; off > 0; off >>= 1)
                v += __shfl_down_sync(0xffffffffu, v, off);
            acc[k] = v;
        }
        __shared__ float ws[9][8];
        const int lane = tid & 31, warp = tid >> 5;
        if (lane == 0) {
#pragma unroll
            for (int k = 0; k < 9; ++k) ws[k][warp] = acc[k];
        }
        __syncthreads();
        if (tid < 9) {
            double d = 0.0;
#pragma unroll
            for (int w = 0; w < 8; ++w) d += (double)ws[tid][w];
            g_part[blockIdx.x][tid] = d;
            __threadfence();   // publish partials
        }
    }

    // ---- arrival: last block finishes ----
    __shared__ int s_last;
    __syncthreads();
    if (tid == 0) s_last = (atomicAdd(&g_cnt, 1) == NB - 1);
    __syncthreads();
    if (!s_last) return;
    __threadfence();   // acquire: see all blocks' g_part

    // ---- final reduce of g_part (256 threads) ----
    double acc[9];
#pragma unroll
    for (int k = 0; k < 9; ++k) acc[k] = 0.0;
    for (int i = tid; i < NB; i += 256) {
#pragma unroll
        for (int k = 0; k < 9; ++k) acc[k] += g_part[i][k];
    }
#pragma unroll
    for (int k = 0; k < 9; ++k) {
        double v = acc[k];
#pragma unroll
        for (int off = 16; off > 0; off >>= 1)
            v += __shfl_down_sync(0xffffffffu, v, off);
        acc[k] = v;
    }
    __shared__ double wd[9][8];
    const int lane = tid & 31, warp = tid >> 5;
    if (lane == 0) {
#pragma unroll
        for (int k = 0; k < 9; ++k) wd[k][warp] = acc[k];
    }
    __syncthreads();
    if (tid != 0) return;

    double S[9];
#pragma unroll
    for (int k = 0; k < 9; ++k) {
        double d = 0.0;
#pragma unroll
        for (int w = 0; w < 8; ++w) d += wd[k][w];
        S[k] = d;
    }

    // ---- covariance (double) ----
    const double Tn = (double)T;
    double a00 = (S[3] - S[0] * S[0] / Tn) / (Tn - 1.0);
    double a11 = (S[4] - S[1] * S[1] / Tn) / (Tn - 1.0);
    double a22 = (S[5] - S[2] * S[2] / Tn) / (Tn - 1.0);
    double a01 = (S[6] - S[0] * S[1] / Tn) / (Tn - 1.0);
    double a02 = (S[7] - S[0] * S[2] / Tn) / (Tn - 1.0);
    double a12 = (S[8] - S[1] * S[2] / Tn) / (Tn - 1.0);

    // ---- largest eigenvalue via Newton on the characteristic cubic ----
    double q = (a00 + a11 + a22) / 3.0;
    double b00 = a00 - q, b11 = a11 - q, b22 = a22 - q;
    double p2 = (b00 * b00 + b11 * b11 + b22 * b22
                 + 2.0 * (a01 * a01 + a02 * a02 + a12 * a12)) / 6.0;
    double vz0, vz1, vz2;
    if (p2 <= 0.0) {
        vz0 = 0.0; vz1 = 0.0; vz2 = 1.0;   // cov ~ multiple of I
    } else {
        double c2 = a00 + a11 + a22;
        double c1 = a00 * a11 + a00 * a22 + a11 * a22
                  - a01 * a01 - a02 * a02 - a12 * a12;
        double c0 = a00 * (a11 * a22 - a12 * a12)
                  - a01 * (a01 * a22 - a12 * a02)
                  + a02 * (a01 * a12 - a11 * a02);
        double lmax = q + 2.0 * sqrt(p2);   // upper bound on lambda_max
#pragma unroll
        for (int it = 0; it < 8; ++it) {
            double f  = ((lmax - c2) * lmax + c1) * lmax - c0;
            double fp = (3.0 * lmax - 2.0 * c2) * lmax + c1;
            if (fabs(fp) > 1e-300) lmax -= f / fp;
        }

        // eigenvector: cross products of rows of (A - lmax I); take the largest
        double m00 = a00 - lmax, m11 = a11 - lmax, m22 = a22 - lmax;
        double c0x = a01 * a12 - m11 * a02;   // r0 x r1
        double c0y = a02 * a01 - m00 * a12;
        double c0z = m00 * m11 - a01 * a01;
        double c1x = a01 * m22 - a12 * a02;   // r0 x r2
        double c1y = a02 * a02 - m00 * m22;
        double c1z = m00 * a12 - a01 * a02;
        double c2x = m11 * m22 - a12 * a12;   // r1 x r2
        double c2y = a12 * a02 - a01 * m22;
        double c2z = a01 * a12 - m11 * a02;
        double n0 = c0x * c0x + c0y * c0y + c0z * c0z;
        double n1 = c1x * c1x + c1y * c1y + c1z * c1z;
        double n2 = c2x * c2x + c2y * c2y + c2z * c2z;
        double vx = c0x, vy = c0y, vzt = c0z, nb = n0;
        if (n1 > nb) { vx = c1x; vy = c1y; vzt = c1z; nb = n1; }
        if (n2 > nb) { vx = c2x; vy = c2y; vzt = c2z; nb = n2; }
        double inv = rsqrt(nb);
        vz0 = vx * inv; vz1 = vy * inv; vz2 = vzt * inv;
    }

    // ---- sign fix vs quaternion-forward, then basis ----
    double qx = (double)x[3 * Ts], qy = (double)x[4 * Ts];
    double qz = (double)x[5 * Ts], qw = (double)x[6 * Ts];
    double zfx = 2.0 * (qx * qz + qw * qy);
    double zfy = 2.0 * (qy * qz - qw * qx);
    double zfz = 1.0 - 2.0 * (qx * qx + qy * qy);
    if (zfx * vz0 + zfy * vz1 + zfz * vz2 < 0.0) { vz0 = -vz0; vz1 = -vz1; vz2 = -vz2; }

    double ux = (double)ra[0], uy = (double)ra[1], uz = (double)ra[2];
    double rx = uy * vz2 - uz * vz1;   // right = up x pca_z
    double ry = uz * vz0 - ux * vz2;
    double rz = ux * vz1 - uy * vz0;
    double fx = ry * uz - rz * uy;     // fwd = right x up
    double fy = rz * ux - rx * uz;
    double fz = rx * uy - ry * ux;

    g_par[0] = (float)rx; g_par[1] = (float)ry; g_par[2] = (float)rz;
    g_par[3] = (float)ux; g_par[4] = (float)uy; g_par[5] = (float)uz;
    g_par[6] = (float)fx; g_par[7] = (float)fy; g_par[8] = (float)fz;
    g_par[9]  = x[0];
    g_par[10] = x[Ts];
    g_par[11] = x[2 * Ts];
    g_cnt = 0;   // self-reset for next graph replay
    __threadfence();
}

// K2: fused output pass — rows 0..2 transformed, rows 7..9 copied to out rows 3..5.
__global__ void __launch_bounds__(256, 8) k_out(const float* __restrict__ x,
                                                float* __restrict__ out, int T) {
    const int nv = T >> 2;
    const size_t Ts = (size_t)T;
    const float b00 = g_par[0], b01 = g_par[1], b02 = g_par[2];
    const float b10 = g_par[3], b11 = g_par[4], b12 = g_par[5];
    const float b20 = g_par[6], b21 = g_par[7], b22 = g_par[8];
    const float r0 = g_par[9], r1 = g_par[10], r2 = g_par[11];

    const float4* __restrict__ x0 = (const float4*)(x);
    const float4* __restrict__ x1 = (const float4*)(x + Ts);
    const float4* __restrict__ x2 = (const float4*)(x + 2 * Ts);
    const float4* __restrict__ a0 = (const float4*)(x + 7 * Ts);
    const float4* __restrict__ a1 = (const float4*)(x + 8 * Ts);
    const float4* __restrict__ a2 = (const float4*)(x + 9 * Ts);
    float4* __restrict__ o0 = (float4*)(out);
    float4* __restrict__ o1 = (float4*)(out + Ts);
    float4* __restrict__ o2 = (float4*)(out + 2 * Ts);
    float4* __restrict__ o3 = (float4*)(out + 3 * Ts);
    float4* __restrict__ o4 = (float4*)(out + 4 * Ts);
    float4* __restrict__ o5 = (float4*)(out + 5 * Ts);

    const int gid = blockIdx.x * 256 + threadIdx.x;
    const int stride = gridDim.x * 256;

    for (int i = gid; i < nv; i += stride) {
        float4 v0 = x0[i], v1 = x1[i], v2 = x2[i];
        float4 w3 = a0[i], w4 = a1[i], w5 = a2[i];
        float c0[4] = {v0.x, v0.y, v0.z, v0.w};
        float c1[4] = {v1.x, v1.y, v1.z, v1.w};
        float c2[4] = {v2.x, v2.y, v2.z, v2.w};
        float w0[4], w1[4], w2[4];
#pragma unroll
        for (int k = 0; k < 4; ++k) {
            float d0 = c0[k] - r0, d1 = c1[k] - r1, d2 = c2[k] - r2;
            w0[k] = b00 * d0 + b01 * d1 + b02 * d2;
            w1[k] = b10 * d0 + b11 * d1 + b12 * d2;
            w2[k] = b20 * d0 + b21 * d1 + b22 * d2;
        }
        o0[i] = make_float4(w0[0], w0[1], w0[2], w0[3]);
        o1[i] = make_float4(w1[0], w1[1], w1[2], w1[3]);
        o2[i] = make_float4(w2[0], w2[1], w2[2], w2[3]);
        o3[i] = w3;
        o4[i] = w4;
        o5[i] = w5;
    }
    for (int t = (nv << 2) + gid; t < T; t += stride) {  // scalar tail
        float d0 = x[t] - r0, d1 = x[Ts + t] - r1, d2 = x[2 * Ts + t] - r2;
        out[t]          = b00 * d0 + b01 * d1 + b02 * d2;
        out[Ts + t]     = b10 * d0 + b11 * d1 + b12 * d2;
        out[2 * Ts + t] = b20 * d0 + b21 * d1 + b22 * d2;
        out[3 * Ts + t] = x[7 * Ts + t];
        out[4 * Ts + t] = x[8 * Ts + t];
        out[5 * Ts + t] = x[9 * Ts + t];
    }
}

extern "C" void kernel_launch(void* const* d_in, const int* in_sizes, int n_in,
                              void* d_out, int out_size) {
    const float* x  = (const float*)d_in[0];
    const float* ra = (const float*)d_in[1];
    float* out = (float*)d_out;
    const int T = in_sizes[0] / 10;
    const int nv = (T >> 2) > 0 ? (T >> 2) : 1;

    int rb = RED_NB, tb = TRF_NB;
    int needed = (nv + 255) / 256;
    if (rb > needed) rb = needed;
    if (tb > needed) tb = needed;
    if (rb < 1) rb = 1;
    if (tb < 1) tb = 1;

    k_reduce<<<rb, 256>>>(x, ra, T);
    k_out<<<tb, 256>>>(x, out, T);
}

// round 13
// speedup vs baseline: 1.0847x; 1.0847x over previous
#include <cuda_runtime.h>

#define RED_NB 912    // 6 blocks/SM x 152 SMs — one exact wave for K1
#define TRF_NB 1216   // 8 blocks/SM x 152 SMs — one exact wave for K2

// Device-global scratch (no allocations allowed).
static __device__ double g_part[RED_NB][9]; // per-block partials
static __device__ float  g_par[12];         // basis rows (right,up,fwd)[9], refPos[3]
static __device__ int    g_cnt;             // arrival counter (self-resetting)

// K1: covariance reduce over rows 0..2 (scalar FFMA — best measured variant);
// last-arriving block finishes the sum and runs the Newton eigensolve.
__global__ void __launch_bounds__(256, 6) k_reduce(const float* __restrict__ x,
                                                   const float* __restrict__ ra, int T) {
    const int nv = T >> 2;
    const size_t Ts = (size_t)T;
    const int tid = threadIdx.x;
    const int gid = blockIdx.x * 256 + tid;
    const int stride = gridDim.x * 256;
    const int NB = gridDim.x;

    {
        const float4* __restrict__ x0 = (const float4*)(x);
        const float4* __restrict__ x1 = (const float4*)(x + Ts);
        const float4* __restrict__ x2 = (const float4*)(x + 2 * Ts);
        float acc[9];
#pragma unroll
        for (int k = 0; k < 9; ++k) acc[k] = 0.0f;

        int i = gid;
        for (; i + stride < nv; i += 2 * stride) {
            const int j = i + stride;
            float4 v0 = x0[i], v1 = x1[i], v2 = x2[i];
            float4 u0 = x0[j], u1 = x1[j], u2 = x2[j];
            float c0[8] = {v0.x, v0.y, v0.z, v0.w, u0.x, u0.y, u0.z, u0.w};
            float c1[8] = {v1.x, v1.y, v1.z, v1.w, u1.x, u1.y, u1.z, u1.w};
            float c2[8] = {v2.x, v2.y, v2.z, v2.w, u2.x, u2.y, u2.z, u2.w};
#pragma unroll
            for (int k = 0; k < 8; ++k) {
                float a = c0[k], b = c1[k], c = c2[k];
                acc[0] += a;     acc[1] += b;     acc[2] += c;
                acc[3] += a * a; acc[4] += b * b; acc[5] += c * c;
                acc[6] += a * b; acc[7] += a * c; acc[8] += b * c;
            }
        }
        for (; i < nv; i += stride) {
            float4 v0 = x0[i], v1 = x1[i], v2 = x2[i];
            float c0[4] = {v0.x, v0.y, v0.z, v0.w};
            float c1[4] = {v1.x, v1.y, v1.z, v1.w};
            float c2[4] = {v2.x, v2.y, v2.z, v2.w};
#pragma unroll
            for (int k = 0; k < 4; ++k) {
                float a = c0[k], b = c1[k], c = c2[k];
                acc[0] += a;     acc[1] += b;     acc[2] += c;
                acc[3] += a * a; acc[4] += b * b; acc[5] += c * c;
                acc[6] += a * b; acc[7] += a * c; acc[8] += b * c;
            }
        }
        for (int t = (nv << 2) + gid; t < T; t += stride) {  // scalar tail
            float a = x[t], b = x[Ts + t], c = x[2 * Ts + t];
            acc[0] += a;     acc[1] += b;     acc[2] += c;
            acc[3] += a * a; acc[4] += b * b; acc[5] += c * c;
            acc[6] += a * b; acc[7] += a * c; acc[8] += b * c;
        }

#pragma unroll
        for (int k = 0; k < 9; ++k) {
            float v = acc[k];
#pragma unroll
            for (int off = 16; off > 0; off >>= 1)
                v += __shfl_down_sync(0xffffffffu, v, off);
            acc[k] = v;
        }
        __shared__ float ws[9][8];
        const int lane = tid & 31, warp = tid >> 5;
        if (lane == 0) {
#pragma unroll
            for (int k = 0; k < 9; ++k) ws[k][warp] = acc[k];
        }
        __syncthreads();
        if (tid < 9) {
            double d = 0.0;
#pragma unroll
            for (int w = 0; w < 8; ++w) d += (double)ws[tid][w];
            g_part[blockIdx.x][tid] = d;
            __threadfence();   // publish partials
        }
    }

    // ---- arrival: last block finishes ----
    __shared__ int s_last;
    __syncthreads();
    if (tid == 0) s_last = (atomicAdd(&g_cnt, 1) == NB - 1);
    __syncthreads();
    if (!s_last) return;
    __threadfence();   // acquire: see all blocks' g_part

    // ---- final reduce of g_part (256 threads) ----
    double acc[9];
#pragma unroll
    for (int k = 0; k < 9; ++k) acc[k] = 0.0;
    for (int i = tid; i < NB; i += 256) {
#pragma unroll
        for (int k = 0; k < 9; ++k) acc[k] += g_part[i][k];
    }
#pragma unroll
    for (int k = 0; k < 9; ++k) {
        double v = acc[k];
#pragma unroll
        for (int off = 16; off > 0; off >>= 1)
            v += __shfl_down_sync(0xffffffffu, v, off);
        acc[k] = v;
    }
    __shared__ double wd[9][8];
    const int lane = tid & 31, warp = tid >> 5;
    if (lane == 0) {
#pragma unroll
        for (int k = 0; k < 9; ++k) wd[k][warp] = acc[k];
    }
    __syncthreads();
    if (tid != 0) return;

    double S[9];
#pragma unroll
    for (int k = 0; k < 9; ++k) {
        double d = 0.0;
#pragma unroll
        for (int w = 0; w < 8; ++w) d += wd[k][w];
        S[k] = d;
    }

    // ---- covariance (double) ----
    const double Tn = (double)T;
    double a00 = (S[3] - S[0] * S[0] / Tn) / (Tn - 1.0);
    double a11 = (S[4] - S[1] * S[1] / Tn) / (Tn - 1.0);
    double a22 = (S[5] - S[2] * S[2] / Tn) / (Tn - 1.0);
    double a01 = (S[6] - S[0] * S[1] / Tn) / (Tn - 1.0);
    double a02 = (S[7] - S[0] * S[2] / Tn) / (Tn - 1.0);
    double a12 = (S[8] - S[1] * S[2] / Tn) / (Tn - 1.0);

    // ---- largest eigenvalue via Newton on the characteristic cubic ----
    double q = (a00 + a11 + a22) / 3.0;
    double b00 = a00 - q, b11 = a11 - q, b22 = a22 - q;
    double p2 = (b00 * b00 + b11 * b11 + b22 * b22
                 + 2.0 * (a01 * a01 + a02 * a02 + a12 * a12)) / 6.0;
    double vz0, vz1, vz2;
    if (p2 <= 0.0) {
        vz0 = 0.0; vz1 = 0.0; vz2 = 1.0;   // cov ~ multiple of I
    } else {
        double c2 = a00 + a11 + a22;
        double c1 = a00 * a11 + a00 * a22 + a11 * a22
                  - a01 * a01 - a02 * a02 - a12 * a12;
        double c0 = a00 * (a11 * a22 - a12 * a12)
                  - a01 * (a01 * a22 - a12 * a02)
                  + a02 * (a01 * a12 - a11 * a02);
        double lmax = q + 2.0 * sqrt(p2);   // upper bound on lambda_max
#pragma unroll
        for (int it = 0; it < 8; ++it) {
            double f  = ((lmax - c2) * lmax + c1) * lmax - c0;
            double fp = (3.0 * lmax - 2.0 * c2) * lmax + c1;
            if (fabs(fp) > 1e-300) lmax -= f / fp;
        }

        // eigenvector: cross products of rows of (A - lmax I); take the largest
        double m00 = a00 - lmax, m11 = a11 - lmax, m22 = a22 - lmax;
        double c0x = a01 * a12 - m11 * a02;   // r0 x r1
        double c0y = a02 * a01 - m00 * a12;
        double c0z = m00 * m11 - a01 * a01;
        double c1x = a01 * m22 - a12 * a02;   // r0 x r2
        double c1y = a02 * a02 - m00 * m22;
        double c1z = m00 * a12 - a01 * a02;
        double c2x = m11 * m22 - a12 * a12;   // r1 x r2
        double c2y = a12 * a02 - a01 * m22;
        double c2z = a01 * a12 - m11 * a02;
        double n0 = c0x * c0x + c0y * c0y + c0z * c0z;
        double n1 = c1x * c1x + c1y * c1y + c1z * c1z;
        double n2 = c2x * c2x + c2y * c2y + c2z * c2z;
        double vx = c0x, vy = c0y, vzt = c0z, nb = n0;
        if (n1 > nb) { vx = c1x; vy = c1y; vzt = c1z; nb = n1; }
        if (n2 > nb) { vx = c2x; vy = c2y; vzt = c2z; nb = n2; }
        double inv = rsqrt(nb);
        vz0 = vx * inv; vz1 = vy * inv; vz2 = vzt * inv;
    }

    // ---- sign fix vs quaternion-forward, then basis ----
    double qx = (double)x[3 * Ts], qy = (double)x[4 * Ts];
    double qz = (double)x[5 * Ts], qw = (double)x[6 * Ts];
    double zfx = 2.0 * (qx * qz + qw * qy);
    double zfy = 2.0 * (qy * qz - qw * qx);
    double zfz = 1.0 - 2.0 * (qx * qx + qy * qy);
    if (zfx * vz0 + zfy * vz1 + zfz * vz2 < 0.0) { vz0 = -vz0; vz1 = -vz1; vz2 = -vz2; }

    double ux = (double)ra[0], uy = (double)ra[1], uz = (double)ra[2];
    double rx = uy * vz2 - uz * vz1;   // right = up x pca_z
    double ry = uz * vz0 - ux * vz2;
    double rz = ux * vz1 - uy * vz0;
    double fx = ry * uz - rz * uy;     // fwd = right x up
    double fy = rz * ux - rx * uz;
    double fz = rx * uy - ry * ux;

    g_par[0] = (float)rx; g_par[1] = (float)ry; g_par[2] = (float)rz;
    g_par[3] = (float)ux; g_par[4] = (float)uy; g_par[5] = (float)uz;
    g_par[6] = (float)fx; g_par[7] = (float)fy; g_par[8] = (float)fz;
    g_par[9]  = x[0];
    g_par[10] = x[Ts];
    g_par[11] = x[2 * Ts];
    g_cnt = 0;   // self-reset for next graph replay
    __threadfence();
}

// K2: fused output pass — REVERSED traversal (hit K1's freshest L2 lines first)
// with streaming hints on the non-reused streams so rows 0..2 stay L2-resident.
__global__ void __launch_bounds__(256, 8) k_out(const float* __restrict__ x,
                                                float* __restrict__ out, int T) {
    const int nv = T >> 2;
    const size_t Ts = (size_t)T;
    const float b00 = g_par[0], b01 = g_par[1], b02 = g_par[2];
    const float b10 = g_par[3], b11 = g_par[4], b12 = g_par[5];
    const float b20 = g_par[6], b21 = g_par[7], b22 = g_par[8];
    const float r0 = g_par[9], r1 = g_par[10], r2 = g_par[11];

    const float4* __restrict__ x0 = (const float4*)(x);
    const float4* __restrict__ x1 = (const float4*)(x + Ts);
    const float4* __restrict__ x2 = (const float4*)(x + 2 * Ts);
    const float4* __restrict__ a0 = (const float4*)(x + 7 * Ts);
    const float4* __restrict__ a1 = (const float4*)(x + 8 * Ts);
    const float4* __restrict__ a2 = (const float4*)(x + 9 * Ts);
    float4* __restrict__ o0 = (float4*)(out);
    float4* __restrict__ o1 = (float4*)(out + Ts);
    float4* __restrict__ o2 = (float4*)(out + 2 * Ts);
    float4* __restrict__ o3 = (float4*)(out + 3 * Ts);
    float4* __restrict__ o4 = (float4*)(out + 4 * Ts);
    float4* __restrict__ o5 = (float4*)(out + 5 * Ts);

    const int gid = blockIdx.x * 256 + threadIdx.x;
    const int stride = gridDim.x * 256;

    for (int i = gid; i < nv; i += stride) {
        const int j = nv - 1 - i;   // reverse: touch K1's warm tail first
        float4 v0 = x0[j], v1 = x1[j], v2 = x2[j];         // reused -> default policy
        float4 w3 = __ldcs(&a0[j]), w4 = __ldcs(&a1[j]), w5 = __ldcs(&a2[j]); // stream
        float c0[4] = {v0.x, v0.y, v0.z, v0.w};
        float c1[4] = {v1.x, v1.y, v1.z, v1.w};
        float c2[4] = {v2.x, v2.y, v2.z, v2.w};
        float w0[4], w1[4], w2[4];
#pragma unroll
        for (int k = 0; k < 4; ++k) {
            float d0 = c0[k] - r0, d1 = c1[k] - r1, d2 = c2[k] - r2;
            w0[k] = b00 * d0 + b01 * d1 + b02 * d2;
            w1[k] = b10 * d0 + b11 * d1 + b12 * d2;
            w2[k] = b20 * d0 + b21 * d1 + b22 * d2;
        }
        __stcs(&o0[j], make_float4(w0[0], w0[1], w0[2], w0[3]));
        __stcs(&o1[j], make_float4(w1[0], w1[1], w1[2], w1[3]));
        __stcs(&o2[j], make_float4(w2[0], w2[1], w2[2], w2[3]));
        __stcs(&o3[j], w3);
        __stcs(&o4[j], w4);
        __stcs(&o5[j], w5);
    }
    for (int t = (nv << 2) + gid; t < T; t += stride) {  // scalar tail
        float d0 = x[t] - r0, d1 = x[Ts + t] - r1, d2 = x[2 * Ts + t] - r2;
        out[t]          = b00 * d0 + b01 * d1 + b02 * d2;
        out[Ts + t]     = b10 * d0 + b11 * d1 + b12 * d2;
        out[2 * Ts + t] = b20 * d0 + b21 * d1 + b22 * d2;
        out[3 * Ts + t] = x[7 * Ts + t];
        out[4 * Ts + t] = x[8 * Ts + t];
        out[5 * Ts + t] = x[9 * Ts + t];
    }
}

extern "C" void kernel_launch(void* const* d_in, const int* in_sizes, int n_in,
                              void* d_out, int out_size) {
    const float* x  = (const float*)d_in[0];
    const float* ra = (const float*)d_in[1];
    float* out = (float*)d_out;
    const int T = in_sizes[0] / 10;
    const int nv = (T >> 2) > 0 ? (T >> 2) : 1;

    int rb = RED_NB, tb = TRF_NB;
    int needed = (nv + 255) / 256;
    if (rb > needed) rb = needed;
    if (tb > needed) tb = needed;
    if (rb < 1) rb = 1;
    if (tb < 1) tb = 1;

    k_reduce<<<rb, 256>>>(x, ra, T);
    k_out<<<tb, 256>>>(x, out, T);
}